// round 12
// baseline (speedup 1.0000x reference)
#include <cuda_runtime.h>
#include <cuda_bf16.h>
#include <cstdint>

#define NT    32768      // B*N total nodes
#define E_CNT 262144     // edges per edge set
#define DH    128
#define NLAY  5
#define TM    64         // edges per tile in edge kernel
#define NTILES (E_CNT / TM)   // 4096
#define EGRID 296        // persistent: 2 blocks/SM

// ---------------- scratch (static device globals; no allocations) ----------
__device__ float g_h   [NT * DH];
__device__ float g_h0  [NT * DH];
__device__ float g_c1  [NT * DH];
__device__ float g_aggm[NT * DH];
__device__ float g_u   [NT * DH];
__device__ float g_v   [NT * DH];
__device__ float g_x   [NT * 3];
__device__ float g_aggx[NT * 3];
__device__ float g_dgi [NT];
__device__ float g_dci [NT];
__device__ __nv_bfloat16 g_WTh[DH * DH];            // W_emb^T hi ([k][n])
__device__ __nv_bfloat16 g_WTl[DH * DH];            // W_emb^T lo
__device__ __nv_bfloat16 g_Bh [NLAY * DH * DH];     // We2 hi ([k][n]) per layer
__device__ __nv_bfloat16 g_Bl [NLAY * DH * DH];     // We2 lo
__device__ __nv_bfloat16 g_Whh[NLAY * 384 * DH];    // Wh hi per layer
__device__ __nv_bfloat16 g_Whl[NLAY * 384 * DH];    // Wh lo
__device__ __nv_bfloat16 g_W1h[NLAY * 256 * DH];    // We1 rows 0..255 hi per layer
__device__ __nv_bfloat16 g_W1l[NLAY * 256 * DH];    // We1 lo

__device__ __forceinline__ float silu_f(float v) {
    return __fdividef(v, 1.0f + __expf(-v));
}

__device__ __forceinline__ void red_v2(float* p, float a, float b) {
    asm volatile("red.global.add.v2.f32 [%0], {%1,%2};"
                 :: "l"(p), "f"(a), "f"(b) : "memory");
}

__device__ __forceinline__ uint32_t smem_u32(const void* p) {
    uint32_t a;
    asm("{ .reg .u64 t; cvta.to.shared.u64 t, %1; cvt.u32.u64 %0, t; }" : "=r"(a) : "l"(p));
    return a;
}

#define NAMED_BAR(id) asm volatile("bar.sync %0, 64;" :: "r"(id) : "memory")

#define LDM_X4(r, a)                                                         \
    asm volatile("ldmatrix.sync.aligned.m8n8.x4.shared.b16 {%0,%1,%2,%3}, [%4];" \
        : "=r"((r)[0]), "=r"((r)[1]), "=r"((r)[2]), "=r"((r)[3]) : "r"(a))
#define LDM_X4T(r, a)                                                        \
    asm volatile("ldmatrix.sync.aligned.m8n8.x4.trans.shared.b16 {%0,%1,%2,%3}, [%4];" \
        : "=r"((r)[0]), "=r"((r)[1]), "=r"((r)[2]), "=r"((r)[3]) : "r"(a))

__device__ __forceinline__ void mma_bf16(float* c, const uint32_t* a, uint32_t b0, uint32_t b1) {
    asm volatile("mma.sync.aligned.m16n8k16.row.col.f32.bf16.bf16.f32 "
        "{%0,%1,%2,%3}, {%4,%5,%6,%7}, {%8,%9}, {%0,%1,%2,%3};"
        : "+f"(c[0]), "+f"(c[1]), "+f"(c[2]), "+f"(c[3])
        : "r"(a[0]), "r"(a[1]), "r"(a[2]), "r"(a[3]), "r"(b0), "r"(b1));
}

__device__ __forceinline__ void bf16_split4(float m0, float m1, float m2, float m3,
                                            uint2& hq, uint2& lq) {
    __nv_bfloat16 h0 = __float2bfloat16(m0), h1 = __float2bfloat16(m1);
    __nv_bfloat16 h2 = __float2bfloat16(m2), h3 = __float2bfloat16(m3);
    __nv_bfloat16 l0 = __float2bfloat16(m0 - __bfloat162float(h0));
    __nv_bfloat16 l1 = __float2bfloat16(m1 - __bfloat162float(h1));
    __nv_bfloat16 l2 = __float2bfloat16(m2 - __bfloat162float(h2));
    __nv_bfloat16 l3 = __float2bfloat16(m3 - __bfloat162float(h3));
    __nv_bfloat162 hp0(h0, h1), hp1(h2, h3), lp0(l0, l1), lp1(l2, l3);
    hq.x = *(uint32_t*)&hp0; hq.y = *(uint32_t*)&hp1;
    lq.x = *(uint32_t*)&lp0; lq.y = *(uint32_t*)&lp1;
}

__device__ __forceinline__ void bf16_split2(float a, float b, uint32_t& hi, uint32_t& lo) {
    __nv_bfloat16 h0 = __float2bfloat16(a), h1 = __float2bfloat16(b);
    __nv_bfloat16 l0 = __float2bfloat16(a - __bfloat162float(h0));
    __nv_bfloat16 l1 = __float2bfloat16(b - __bfloat162float(h1));
    __nv_bfloat162 hp(h0, h1), lp(l0, l1);
    hi = *(uint32_t*)&hp; lo = *(uint32_t*)&lp;
}

#define ASTRIDE  272     // bytes per bf16 row: ldmatrix conflict-free

// common MMA macro
#define MMA_K128(accArr, aAddrH, aAddrL, bAddrH, bAddrL)                     \
    _Pragma("unroll")                                                        \
    for (int kc = 0; kc < 8; kc++) {                                         \
        uint32_t aH[4], aL[4];                                               \
        LDM_X4(aH, (aAddrH) + kc * 32);                                      \
        LDM_X4(aL, (aAddrL) + kc * 32);                                      \
        const uint32_t bko = (uint32_t)(kc * 16 * ASTRIDE);                  \
        _Pragma("unroll")                                                    \
        for (int nt2 = 0; nt2 < 4; nt2++) {                                  \
            uint32_t bH[4], bL[4];                                           \
            LDM_X4T(bH, (bAddrH) + bko + nt2 * 32);                          \
            LDM_X4T(bL, (bAddrL) + bko + nt2 * 32);                          \
            mma_bf16(accArr[2 * nt2],     aH, bH[0], bH[1]);                 \
            mma_bf16(accArr[2 * nt2],     aH, bL[0], bL[1]);                 \
            mma_bf16(accArr[2 * nt2],     aL, bH[0], bH[1]);                 \
            mma_bf16(accArr[2 * nt2 + 1], aH, bH[2], bH[3]);                 \
            mma_bf16(accArr[2 * nt2 + 1], aH, bL[2], bL[3]);                 \
            mma_bf16(accArr[2 * nt2 + 1], aL, bH[2], bH[3]);                 \
        }                                                                    \
    }

// load a 128x128 bf16 hi/lo plane pair from global into smem (all 256 thr)
#define LOAD_B_PLANES(smemBase, offH, offL, srcH, srcL)                      \
    _Pragma("unroll")                                                        \
    for (int it = 0; it < 16; it++) {                                        \
        int task = threadIdx.x + 256 * it;                                   \
        int r = task >> 5, c4 = task & 31;                                   \
        uint2 hq = *reinterpret_cast<const uint2*>(&(srcH)[r * DH + c4 * 4]);\
        uint2 lq = *reinterpret_cast<const uint2*>(&(srcL)[r * DH + c4 * 4]);\
        *reinterpret_cast<uint2*>((smemBase) + (offH) + r * ASTRIDE + c4 * 8) = hq; \
        *reinterpret_cast<uint2*>((smemBase) + (offL) + r * ASTRIDE + c4 * 8) = lq; \
    }

// ---------------- small helper kernels -------------------------------------
__global__ void prep_kernel(const float* __restrict__ W_emb, const float* __restrict__ We2,
                            const float* __restrict__ Wh, const float* __restrict__ We1,
                            __nv_bfloat16* __restrict__ WTh, __nv_bfloat16* __restrict__ WTl,
                            __nv_bfloat16* __restrict__ Bh, __nv_bfloat16* __restrict__ Bl,
                            __nv_bfloat16* __restrict__ Whh, __nv_bfloat16* __restrict__ Whl,
                            __nv_bfloat16* __restrict__ W1h, __nv_bfloat16* __restrict__ W1l) {
    int b = blockIdx.x, tid = threadIdx.x;
    if (b < 64) {
        int i = b * 256 + tid;
        int k = i >> 7, j = i & 127;
        float v = W_emb[j * DH + k];
        __nv_bfloat16 h = __float2bfloat16(v);
        WTh[i] = h;
        WTl[i] = __float2bfloat16(v - __bfloat162float(h));
    } else if (b < 384) {
        int i = (b - 64) * 256 + tid;
        if (i < NLAY * DH * DH) {
            float v = We2[i];
            __nv_bfloat16 h = __float2bfloat16(v);
            Bh[i] = h;
            Bl[i] = __float2bfloat16(v - __bfloat162float(h));
        }
    } else if (b < 1344) {
        int i = (b - 384) * 256 + tid;
        if (i < NLAY * 384 * DH) {
            float v = Wh[i];
            __nv_bfloat16 h = __float2bfloat16(v);
            Whh[i] = h;
            Whl[i] = __float2bfloat16(v - __bfloat162float(h));
        }
    } else {
        int i = (b - 1344) * 256 + tid;
        if (i < NLAY * 256 * DH) {
            int l = i / (256 * DH), r = i % (256 * DH);
            float v = We1[(size_t)l * 257 * DH + r];
            __nv_bfloat16 h = __float2bfloat16(v);
            W1h[i] = h;
            W1l[i] = __float2bfloat16(v - __bfloat162float(h));
        }
    }
}

__global__ void deg_kernel(const int* __restrict__ dst, float* __restrict__ deg) {
    int e = blockIdx.x * blockDim.x + threadIdx.x;
    if (e < E_CNT) atomicAdd(&deg[dst[e]], 1.0f);
}

__global__ void deginv_kernel(float* __restrict__ deg) {
    int i = blockIdx.x * blockDim.x + threadIdx.x;
    if (i < NT) deg[i] = 1.0f / fmaxf(deg[i], 1.0f);
}

// xupd also zeroes aggx after use
__global__ void xupd_kernel(const float* __restrict__ x0, const float* __restrict__ xin,
                            float* __restrict__ xout,
                            float* __restrict__ aggx, const float* __restrict__ dinv) {
    int i = blockIdx.x * blockDim.x + threadIdx.x;
    if (i < NT * 3) {
        float a = aggx[i];
        aggx[i] = 0.f;
        xout[i] = 0.25f * x0[i] + 0.75f * xin[i] + a * dinv[i / 3];
    }
}

// ============ shared smem map for the 64-row GEMM kernels ===================
#define NO_BIAS  0
#define NO_DINV  512
#define NO_AH    1024
#define NO_AL    (NO_AH + 64 * ASTRIDE)
#define NO_BH    (NO_AL + 64 * ASTRIDE)
#define NO_BL    (NO_BH + 128 * ASTRIDE)
#define N_SMEM   (NO_BL + 128 * ASTRIDE)

// ============ embed + layer-0 UV: h=feat@Wemb^T; U=h@A0; V=h@B0+be1 =========
__global__ __launch_bounds__(256) void embeduv_kernel(
    const float* __restrict__ feat,
    const __nv_bfloat16* __restrict__ WTh, const __nv_bfloat16* __restrict__ WTl,
    const __nv_bfloat16* __restrict__ W1h, const __nv_bfloat16* __restrict__ W1l,
    const float* __restrict__ be1,
    float* __restrict__ h, float* __restrict__ h0,
    float* __restrict__ U, float* __restrict__ V)
{
    extern __shared__ char smem[];
    const int tid = threadIdx.x;
    const int lane = tid & 31, warp = tid >> 5;
    const int r0 = blockIdx.x * 64;
    const int rg = warp >> 1, ch = warp & 1;

    float* bias_s = (float*)(smem + NO_BIAS);

    // A = feat rows (bf16 split)
    #pragma unroll
    for (int it = 0; it < 8; it++) {
        int task = tid + 256 * it;
        int r = task >> 5, c4 = task & 31;
        float4 v = *reinterpret_cast<const float4*>(&feat[(size_t)(r0 + r) * DH + c4 * 4]);
        uint2 hq, lq;
        bf16_split4(v.x, v.y, v.z, v.w, hq, lq);
        *reinterpret_cast<uint2*>(smem + NO_AH + r * ASTRIDE + c4 * 8) = hq;
        *reinterpret_cast<uint2*>(smem + NO_AL + r * ASTRIDE + c4 * 8) = lq;
    }
    LOAD_B_PLANES(smem, NO_BH, NO_BL, WTh, WTl)
    __syncthreads();

    const uint32_t sb = smem_u32(smem);
    const uint32_t aAddrH = sb + NO_AH + (rg * 16 + (lane & 15)) * ASTRIDE + (lane >> 4) * 16;
    const uint32_t aAddrL = sb + NO_AL + (rg * 16 + (lane & 15)) * ASTRIDE + (lane >> 4) * 16;
    const uint32_t bAddrH = sb + NO_BH + (lane & 15) * ASTRIDE + (lane >> 4) * 16 + ch * 128;
    const uint32_t bAddrL = sb + NO_BL + (lane & 15) * ASTRIDE + (lane >> 4) * 16 + ch * 128;
    const int g = lane >> 2, c2 = (lane & 3) * 2;

    float acc[8][4];
    #pragma unroll
    for (int t = 0; t < 8; t++)
        #pragma unroll
        for (int q = 0; q < 4; q++) acc[t][q] = 0.f;

    MMA_K128(acc, aAddrH, aAddrL, bAddrH, bAddrL)
    __syncthreads();   // all ldmatrix reads of feat-A done before overwrite

    // write h/h0 and rebuild A planes from h fragments
    #pragma unroll
    for (int nt = 0; nt < 8; nt++) {
        int col = ch * 64 + nt * 8 + c2;
        #pragma unroll
        for (int hrow = 0; hrow < 2; hrow++) {
            int row = rg * 16 + g + hrow * 8;
            float v0 = acc[nt][hrow * 2 + 0], v1 = acc[nt][hrow * 2 + 1];
            size_t o = (size_t)(r0 + row) * DH + col;
            *reinterpret_cast<float2*>(&h[o])  = make_float2(v0, v1);
            *reinterpret_cast<float2*>(&h0[o]) = make_float2(v0, v1);
            uint32_t hi, lo;
            bf16_split2(v0, v1, hi, lo);
            *reinterpret_cast<uint32_t*>(smem + NO_AH + row * ASTRIDE + col * 2) = hi;
            *reinterpret_cast<uint32_t*>(smem + NO_AL + row * ASTRIDE + col * 2) = lo;
        }
    }

    // two halves: U (bias 0), V (bias be1)
    #pragma unroll
    for (int half = 0; half < 2; half++) {
        __syncthreads();   // A writes visible; prev-half ldmatrix done
        if (tid < 128) bias_s[tid] = half ? be1[tid] : 0.f;
        LOAD_B_PLANES(smem, NO_BH, NO_BL, W1h + (size_t)half * 128 * DH,
                                          W1l + (size_t)half * 128 * DH)
        __syncthreads();
        #pragma unroll
        for (int t = 0; t < 8; t++)
            #pragma unroll
            for (int q = 0; q < 4; q++) acc[t][q] = 0.f;
        MMA_K128(acc, aAddrH, aAddrL, bAddrH, bAddrL)
        float* out = half ? V : U;
        #pragma unroll
        for (int nt = 0; nt < 8; nt++) {
            int col = ch * 64 + nt * 8 + c2;
            float b0 = bias_s[col], b1 = bias_s[col + 1];
            #pragma unroll
            for (int hrow = 0; hrow < 2; hrow++) {
                int row = r0 + rg * 16 + g + hrow * 8;
                size_t o = (size_t)row * DH + col;
                *reinterpret_cast<float2*>(&out[o]) =
                    make_float2(acc[nt][hrow * 2 + 0] + b0, acc[nt][hrow * 2 + 1] + b1);
            }
        }
    }
}

// ============ persistent edge kernel: named-barrier decoupled rg groups =====
#define ES_BE2   0
#define ES_WX    512
#define ES_W256  1024
#define ES_PS    1536
#define ES_AH    1792
#define ES_AL    (ES_AH + 64 * ASTRIDE)
#define ES_BH    (ES_AL + 64 * ASTRIDE)
#define ES_BL    (ES_BH + 128 * ASTRIDE)
#define E_SMEM   (ES_BL + 128 * ASTRIDE)     // 106240

__global__ __launch_bounds__(256) void edge_mma_kernel(
    const int* __restrict__ src, const int* __restrict__ dst,
    const float* __restrict__ x,
    const float* __restrict__ U, const float* __restrict__ V,
    const float* __restrict__ w256,
    const __nv_bfloat16* __restrict__ Bh, const __nv_bfloat16* __restrict__ Bl,
    const float* __restrict__ be2, const float* __restrict__ Wx,
    float* __restrict__ aggx, float* __restrict__ aggm)
{
    extern __shared__ char smem[];
    const int tid = threadIdx.x;
    const int lane = tid & 31, warp = tid >> 5;
    const int rg = warp >> 1, ch = warp & 1;

    float* be2_s  = (float*)(smem + ES_BE2);
    float* wx_s   = (float*)(smem + ES_WX);
    float* w256_s = (float*)(smem + ES_W256);
    float* p_s    = (float*)(smem + ES_PS);

    if (tid < 128) {
        be2_s[tid]  = be2[tid];
        wx_s[tid]   = Wx[tid];
        w256_s[tid] = w256[tid];
    }
    if (tid < 64) p_s[tid] = 0.f;
    LOAD_B_PLANES(smem, ES_BH, ES_BL, Bh, Bl)
    __syncthreads();

    const uint32_t sb = smem_u32(smem);
    const uint32_t aAddrH = sb + ES_AH + (rg * 16 + (lane & 15)) * ASTRIDE + (lane >> 4) * 16;
    const uint32_t aAddrL = sb + ES_AL + (rg * 16 + (lane & 15)) * ASTRIDE + (lane >> 4) * 16;
    const uint32_t bAddrH = sb + ES_BH + (lane & 15) * ASTRIDE + (lane >> 4) * 16 + ch * 128;
    const uint32_t bAddrL = sb + ES_BL + (lane & 15) * ASTRIDE + (lane >> 4) * 16 + ch * 128;
    const int g = lane >> 2, cp = lane & 3;
    const float4 w256r = *reinterpret_cast<const float4*>(&w256_s[lane * 4]);
    const int barid = rg + 1;

    for (int tile = blockIdx.x; tile < NTILES; tile += gridDim.x) {
        int sreg = 0, dreg = 0;
        float dx0 = 0.f, dx1 = 0.f, dx2 = 0.f, d2 = 0.f;
        if (lane < 16) {
            int e = tile * TM + rg * 16 + lane;
            sreg = src[e]; dreg = dst[e];
            dx0 = x[sreg * 3 + 0] - x[dreg * 3 + 0];
            dx1 = x[sreg * 3 + 1] - x[dreg * 3 + 1];
            dx2 = x[sreg * 3 + 2] - x[dreg * 3 + 2];
            d2 = dx0 * dx0 + dx1 * dx1 + dx2 * dx2;
        }

        #pragma unroll
        for (int it = 0; it < 8; it++) {
            int rl = ch * 8 + it;
            int srcr = __shfl_sync(0xffffffffu, sreg, rl);
            int dstr = __shfl_sync(0xffffffffu, dreg, rl);
            float d2r = __shfl_sync(0xffffffffu, d2, rl);
            const float4 uu = *reinterpret_cast<const float4*>(&U[(size_t)srcr * DH + lane * 4]);
            const float4 vv = *reinterpret_cast<const float4*>(&V[(size_t)dstr * DH + lane * 4]);
            uint2 hq, lq;
            bf16_split4(silu_f(uu.x + vv.x + d2r * w256r.x), silu_f(uu.y + vv.y + d2r * w256r.y),
                        silu_f(uu.z + vv.z + d2r * w256r.z), silu_f(uu.w + vv.w + d2r * w256r.w),
                        hq, lq);
            int row = rg * 16 + rl;
            *reinterpret_cast<uint2*>(smem + ES_AH + row * ASTRIDE + lane * 8) = hq;
            *reinterpret_cast<uint2*>(smem + ES_AL + row * ASTRIDE + lane * 8) = lq;
        }
        NAMED_BAR(barid);

        float acc[8][4];
        #pragma unroll
        for (int t = 0; t < 8; t++)
            #pragma unroll
            for (int q = 0; q < 4; q++) acc[t][q] = 0.f;

        MMA_K128(acc, aAddrH, aAddrL, bAddrH, bAddrL)

        {
            int dn_g  = __shfl_sync(0xffffffffu, dreg, g);
            int dn_g8 = __shfl_sync(0xffffffffu, dreg, g + 8);
            float pg = 0.f, pg8 = 0.f;
            #pragma unroll
            for (int nt = 0; nt < 8; nt++) {
                int c = ch * 64 + nt * 8 + cp * 2;
                float b0 = be2_s[c], b1 = be2_s[c + 1];
                float w0 = wx_s[c],  w1 = wx_s[c + 1];
                float m0 = silu_f(acc[nt][0] + b0);
                float m1 = silu_f(acc[nt][1] + b1);
                red_v2(&aggm[(size_t)dn_g * DH + c], m0, m1);
                pg += m0 * w0 + m1 * w1;
                float m2 = silu_f(acc[nt][2] + b0);
                float m3 = silu_f(acc[nt][3] + b1);
                red_v2(&aggm[(size_t)dn_g8 * DH + c], m2, m3);
                pg8 += m2 * w0 + m3 * w1;
            }
            pg  += __shfl_xor_sync(0xffffffffu, pg, 1);
            pg  += __shfl_xor_sync(0xffffffffu, pg, 2);
            pg8 += __shfl_xor_sync(0xffffffffu, pg8, 1);
            pg8 += __shfl_xor_sync(0xffffffffu, pg8, 2);
            if (cp == 0) {
                atomicAdd(&p_s[rg * 16 + g], pg);
                atomicAdd(&p_s[rg * 16 + g + 8], pg8);
            }
        }
        NAMED_BAR(barid);

        if (ch == 0 && lane < 16) {
            float coef = tanhf(p_s[rg * 16 + lane]);
            p_s[rg * 16 + lane] = 0.f;
            atomicAdd(&aggx[dreg * 3 + 0], dx0 * coef);
            atomicAdd(&aggx[dreg * 3 + 1], dx1 * coef);
            atomicAdd(&aggx[dreg * 3 + 2], dx2 * coef);
        }
    }
}

// ============ node kernel; optional fused next-layer UV tail ================
template<bool SUB, bool DOUV>
__global__ __launch_bounds__(256) void node_mma_kernel(
    const float* __restrict__ h, float* __restrict__ aggm,   // aggm zeroed after read
    const float* __restrict__ h0, const float* __restrict__ dinv,
    const __nv_bfloat16* __restrict__ Whh, const __nv_bfloat16* __restrict__ Whl,
    const float* __restrict__ bias,
    const float* __restrict__ c1, float* __restrict__ out,
    const __nv_bfloat16* __restrict__ W1h, const __nv_bfloat16* __restrict__ W1l,
    const float* __restrict__ be1, float* __restrict__ U, float* __restrict__ V)
{
    extern __shared__ char smem[];
    const int tid = threadIdx.x;
    const int lane = tid & 31, warp = tid >> 5;
    const int r0 = blockIdx.x * 64;

    float* bias_s = (float*)(smem + NO_BIAS);
    float* dinv_s = (float*)(smem + NO_DINV);
    if (tid < 128) bias_s[tid] = bias[tid];
    if (tid < 64)  dinv_s[tid] = dinv[r0 + tid];

    const int rg = warp >> 1, ch = warp & 1;
    float acc[8][4];
    #pragma unroll
    for (int t = 0; t < 8; t++)
        #pragma unroll
        for (int q = 0; q < 4; q++) acc[t][q] = 0.f;

    const uint32_t sb = smem_u32(smem);
    const uint32_t aAddrH = sb + NO_AH + (rg * 16 + (lane & 15)) * ASTRIDE + (lane >> 4) * 16;
    const uint32_t aAddrL = sb + NO_AL + (rg * 16 + (lane & 15)) * ASTRIDE + (lane >> 4) * 16;
    const uint32_t bAddrH = sb + NO_BH + (lane & 15) * ASTRIDE + (lane >> 4) * 16 + ch * 128;
    const uint32_t bAddrL = sb + NO_BL + (lane & 15) * ASTRIDE + (lane >> 4) * 16 + ch * 128;

    for (int chunk = 0; chunk < 3; chunk++) {
        __syncthreads();
        const float* sp = (chunk == 0) ? h : (chunk == 1) ? aggm : h0;
        #pragma unroll
        for (int it = 0; it < 8; it++) {
            int task = tid + 256 * it;
            int r = task >> 5, c4 = task & 31;
            size_t off = (size_t)(r0 + r) * DH + c4 * 4;
            float4 v = *reinterpret_cast<const float4*>(&sp[off]);
            if (chunk == 1) {
                float s = dinv_s[r];
                v.x *= s; v.y *= s; v.z *= s; v.w *= s;
                *reinterpret_cast<float4*>(&aggm[off]) = make_float4(0.f, 0.f, 0.f, 0.f);
            }
            uint2 hq, lq;
            bf16_split4(v.x, v.y, v.z, v.w, hq, lq);
            *reinterpret_cast<uint2*>(smem + NO_AH + r * ASTRIDE + c4 * 8) = hq;
            *reinterpret_cast<uint2*>(smem + NO_AL + r * ASTRIDE + c4 * 8) = lq;
        }
        LOAD_B_PLANES(smem, NO_BH, NO_BL, Whh + (size_t)chunk * 128 * DH,
                                          Whl + (size_t)chunk * 128 * DH)
        __syncthreads();

        MMA_K128(acc, aAddrH, aAddrL, bAddrH, bAddrL)
    }

    if (DOUV) __syncthreads();   // all ldmatrix done before A-plane overwrite

    const int g = lane >> 2, c2 = (lane & 3) * 2;
    #pragma unroll
    for (int nt = 0; nt < 8; nt++) {
        int col = ch * 64 + nt * 8 + c2;
        float b0 = bias_s[col], b1 = bias_s[col + 1];
        #pragma unroll
        for (int hrow = 0; hrow < 2; hrow++) {
            int row = rg * 16 + g + hrow * 8;
            size_t o = (size_t)(r0 + row) * DH + col;
            float v0 = silu_f(acc[nt][hrow * 2 + 0] + b0);
            float v1 = silu_f(acc[nt][hrow * 2 + 1] + b1);
            if (SUB) { v0 -= c1[o]; v1 -= c1[o + 1]; }
            *reinterpret_cast<float2*>(&out[o]) = make_float2(v0, v1);
            if (DOUV) {
                uint32_t hi, lo;
                bf16_split2(v0, v1, hi, lo);
                *reinterpret_cast<uint32_t*>(smem + NO_AH + row * ASTRIDE + col * 2) = hi;
                *reinterpret_cast<uint32_t*>(smem + NO_AL + row * ASTRIDE + col * 2) = lo;
            }
        }
    }

    if (DOUV) {
        #pragma unroll
        for (int half = 0; half < 2; half++) {
            __syncthreads();   // A writes visible; prev-half ldmatrix done
            if (tid < 128) bias_s[tid] = half ? be1[tid] : 0.f;
            LOAD_B_PLANES(smem, NO_BH, NO_BL, W1h + (size_t)half * 128 * DH,
                                              W1l + (size_t)half * 128 * DH)
            __syncthreads();
            #pragma unroll
            for (int t = 0; t < 8; t++)
                #pragma unroll
                for (int q = 0; q < 4; q++) acc[t][q] = 0.f;
            MMA_K128(acc, aAddrH, aAddrL, bAddrH, bAddrL)
            float* uvout = half ? V : U;
            #pragma unroll
            for (int nt = 0; nt < 8; nt++) {
                int col = ch * 64 + nt * 8 + c2;
                float b0 = bias_s[col], b1 = bias_s[col + 1];
                #pragma unroll
                for (int hrow = 0; hrow < 2; hrow++) {
                    int row = r0 + rg * 16 + g + hrow * 8;
                    size_t o = (size_t)row * DH + col;
                    *reinterpret_cast<float2*>(&uvout[o]) =
                        make_float2(acc[nt][hrow * 2 + 0] + b0, acc[nt][hrow * 2 + 1] + b1);
                }
            }
        }
    }
}

// ---------------- pooling + FC head ----------------------------------------
__global__ void pool_kernel(const float* __restrict__ h, const float* __restrict__ cv,
                            const float* __restrict__ Wfc, const float* __restrict__ bfc,
                            const float* __restrict__ Wout, const float* __restrict__ bout,
                            float* __restrict__ out)
{
    int b = blockIdx.x, j = threadIdx.x;
    __shared__ float z[DH];
    __shared__ float rs[4];
    float acc = 0.f, cnt = 0.f;
    for (int n = 0; n < 512; n++) {
        float v = cv[b * 512 + n];
        acc += h[(size_t)(b * 512 + n) * DH + j] * v;
        cnt += v;
    }
    z[j] = acc / cnt;
    __syncthreads();
    for (int i = 0; i < 3; i++) {
        const float* Wp = Wfc + i * DH * DH;
        float s = bfc[i * DH + j];
        for (int k = 0; k < DH; k++) s += z[k] * Wp[k * DH + j];
        s = fmaxf(s, 0.f);
        __syncthreads();
        z[j] = s;
        __syncthreads();
    }
    float p = z[j] * Wout[j];
    #pragma unroll
    for (int off = 16; off > 0; off >>= 1) p += __shfl_xor_sync(0xffffffffu, p, off);
    if ((j & 31) == 0) rs[j >> 5] = p;
    __syncthreads();
    if (j == 0) out[b] = 1.f / (1.f + expf(-(rs[0] + rs[1] + rs[2] + rs[3] + bout[0])));
}

// ---------------- launch -----------------------------------------------------
extern "C" void kernel_launch(void* const* d_in, const int* in_sizes, int n_in,
                              void* d_out, int out_size)
{
    const float* feat      = (const float*)d_in[0];
    const float* coords    = (const float*)d_in[1];
    const float* c_valid   = (const float*)d_in[2];
    const int*   edge_src  = (const int*)d_in[3];
    const int*   edge_dst  = (const int*)d_in[4];
    const int*   cross_src = (const int*)d_in[5];
    const int*   cross_dst = (const int*)d_in[6];
    const float* W_emb     = (const float*)d_in[7];
    const float* We1       = (const float*)d_in[8];
    const float* be1       = (const float*)d_in[9];
    const float* We2       = (const float*)d_in[10];
    const float* be2       = (const float*)d_in[11];
    const float* Wx        = (const float*)d_in[12];
    const float* Wh        = (const float*)d_in[13];
    const float* bh        = (const float*)d_in[14];
    const float* Wfc       = (const float*)d_in[15];
    const float* bfc       = (const float*)d_in[16];
    const float* Wout      = (const float*)d_in[17];
    const float* bout      = (const float*)d_in[18];
    float* out = (float*)d_out;

    float *p_h, *p_h0, *p_c1, *p_aggm, *p_u, *p_v, *p_x, *p_aggx, *p_dgi, *p_dci;
    __nv_bfloat16 *p_WTh, *p_WTl, *p_Bh, *p_Bl, *p_Whh, *p_Whl, *p_W1h, *p_W1l;
    cudaGetSymbolAddress((void**)&p_h,    g_h);
    cudaGetSymbolAddress((void**)&p_h0,   g_h0);
    cudaGetSymbolAddress((void**)&p_c1,   g_c1);
    cudaGetSymbolAddress((void**)&p_aggm, g_aggm);
    cudaGetSymbolAddress((void**)&p_u,    g_u);
    cudaGetSymbolAddress((void**)&p_v,    g_v);
    cudaGetSymbolAddress((void**)&p_x,    g_x);
    cudaGetSymbolAddress((void**)&p_aggx, g_aggx);
    cudaGetSymbolAddress((void**)&p_dgi,  g_dgi);
    cudaGetSymbolAddress((void**)&p_dci,  g_dci);
    cudaGetSymbolAddress((void**)&p_WTh,  g_WTh);
    cudaGetSymbolAddress((void**)&p_WTl,  g_WTl);
    cudaGetSymbolAddress((void**)&p_Bh,   g_Bh);
    cudaGetSymbolAddress((void**)&p_Bl,   g_Bl);
    cudaGetSymbolAddress((void**)&p_Whh,  g_Whh);
    cudaGetSymbolAddress((void**)&p_Whl,  g_Whl);
    cudaGetSymbolAddress((void**)&p_W1h,  g_W1h);
    cudaGetSymbolAddress((void**)&p_W1l,  g_W1l);

    cudaFuncSetAttribute(edge_mma_kernel, cudaFuncAttributeMaxDynamicSharedMemorySize, E_SMEM);
    cudaFuncSetAttribute(embeduv_kernel,  cudaFuncAttributeMaxDynamicSharedMemorySize, N_SMEM);
    cudaFuncSetAttribute(node_mma_kernel<false, false>, cudaFuncAttributeMaxDynamicSharedMemorySize, N_SMEM);
    cudaFuncSetAttribute(node_mma_kernel<true,  true>,  cudaFuncAttributeMaxDynamicSharedMemorySize, N_SMEM);
    cudaFuncSetAttribute(node_mma_kernel<true,  false>, cudaFuncAttributeMaxDynamicSharedMemorySize, N_SMEM);

    // Launch order keeps the first edge_mma_kernel at profiled slot #6 (-s 5 -c 1):
    // memset(1), memset(2), prep(3), embeduv(4), memset-dgi(5), edge(6).
    cudaMemsetAsync(p_aggx, 0, NT * 3 * sizeof(float));
    cudaMemsetAsync(p_aggm, 0, (size_t)NT * DH * sizeof(float));
    prep_kernel<<<1984, 256>>>(W_emb, We2, Wh, We1, p_WTh, p_WTl, p_Bh, p_Bl,
                               p_Whh, p_Whl, p_W1h, p_W1l);
    embeduv_kernel<<<NT / 64, 256, N_SMEM>>>(feat, p_WTh, p_WTl, p_W1h, p_W1l, be1,
                                             p_h, p_h0, p_u, p_v);
    cudaMemsetAsync(p_dgi, 0, NT * sizeof(float));   // slot 5 (cheap)

    const float* xin = coords;
    for (int k = 0; k < NLAY; k++) {
        const float* We1k = We1 + (size_t)k * 257 * DH;
        const float* w256 = We1k + 256 * DH;
        const float* be2k = be2 + k * DH;
        const float* Wxk  = Wx + k * DH;
        const float* bhk  = bh + k * DH;
        const __nv_bfloat16* Bhk  = p_Bh + (size_t)k * DH * DH;
        const __nv_bfloat16* Blk  = p_Bl + (size_t)k * DH * DH;
        const __nv_bfloat16* Whhk = p_Whh + (size_t)k * 384 * DH;
        const __nv_bfloat16* Whlk = p_Whl + (size_t)k * 384 * DH;

        // pass 1: graph edges
        edge_mma_kernel<<<EGRID, 256, E_SMEM>>>(edge_src, edge_dst, xin, p_u, p_v,
                                                w256, Bhk, Blk, be2k, Wxk, p_aggx, p_aggm);
        if (k == 0) {
            cudaMemsetAsync(p_dci, 0, NT * sizeof(float));
            deg_kernel<<<E_CNT / 256, 256>>>(edge_dst,  p_dgi);
            deg_kernel<<<E_CNT / 256, 256>>>(cross_dst, p_dci);
            deginv_kernel<<<NT / 256, 256>>>(p_dgi);
            deginv_kernel<<<NT / 256, 256>>>(p_dci);
        }
        xupd_kernel<<<NT * 3 / 256, 256>>>(coords, xin, p_x, p_aggx, p_dgi);
        xin = p_x;
        node_mma_kernel<false, false><<<NT / 64, 256, N_SMEM>>>(
            p_h, p_aggm, p_h0, p_dgi, Whhk, Whlk, bhk, nullptr, p_c1,
            nullptr, nullptr, nullptr, nullptr, nullptr);

        // pass 2: cross edges -> h = c2 - c1 (in place); fused next-layer UV
        edge_mma_kernel<<<EGRID, 256, E_SMEM>>>(cross_src, cross_dst, p_x, p_u, p_v,
                                                w256, Bhk, Blk, be2k, Wxk, p_aggx, p_aggm);
        xupd_kernel<<<NT * 3 / 256, 256>>>(coords, p_x, p_x, p_aggx, p_dci);
        if (k < NLAY - 1) {
            const __nv_bfloat16* W1hn = p_W1h + (size_t)(k + 1) * 256 * DH;
            const __nv_bfloat16* W1ln = p_W1l + (size_t)(k + 1) * 256 * DH;
            const float* be1n = be1 + (k + 1) * DH;
            node_mma_kernel<true, true><<<NT / 64, 256, N_SMEM>>>(
                p_h, p_aggm, p_h0, p_dci, Whhk, Whlk, bhk, p_c1, p_h,
                W1hn, W1ln, be1n, p_u, p_v);
        } else {
            node_mma_kernel<true, false><<<NT / 64, 256, N_SMEM>>>(
                p_h, p_aggm, p_h0, p_dci, Whhk, Whlk, bhk, p_c1, p_h,
                nullptr, nullptr, nullptr, nullptr, nullptr);
        }
    }

    pool_kernel<<<64, 128>>>(p_h, c_valid, Wfc, bfc, Wout, bout, out);
}